// round 1
// baseline (speedup 1.0000x reference)
#include <cuda_runtime.h>
#include <math.h>

#define TT 2048
#define DIM 2048
#define NEXP 32
#define TOPK 4
#define INTER 1024
#define SHIN 2048
#define NA (TT*TOPK)              /* 8192 assignments */
#define BM 128
#define MAXTILES (NA/BM + NEXP)   /* 96 */

// ---------------- device scratch (static, no allocation) ----------------
__device__ int   g_topi[TT*TOPK];
__device__ float g_topw[TT*TOPK];
__device__ int   g_cnt[NEXP];
__device__ int   g_off[NEXP+1];
__device__ int   g_tok[NA];
__device__ float g_wt[NA];
__device__ int   g_tile_e[MAXTILES];
__device__ int   g_tile_r0[MAXTILES];
__device__ int   g_tile_n[MAXTILES];
__device__ int   g_ntiles;
__device__ float g_h[(size_t)NA*INTER];   // 33.5 MB routed hidden
__device__ float g_hs[(size_t)TT*SHIN];   // 16.8 MB shared hidden

__device__ __forceinline__ float silu_f(float v) {
    return v / (1.0f + expf(-v));
}

// ---------------- kernel 0: zero the expert counters ----------------
__global__ void k_zero() {
    if (threadIdx.x < NEXP) g_cnt[threadIdx.x] = 0;
}

// ---------------- kernel 1: gate (fp32 exact) + softmax + top-4 ----------------
__global__ __launch_bounds__(128) void k_gate(const float* __restrict__ x,
                                              const float* __restrict__ gw) {
    __shared__ float sx[DIM];
    __shared__ float slog[NEXP];
    int t = blockIdx.x;
    const float* xr = x + (size_t)t * DIM;
    for (int i = threadIdx.x * 4; i < DIM; i += 128 * 4)
        *(float4*)(sx + i) = *(const float4*)(xr + i);
    __syncthreads();

    int e = threadIdx.x >> 2, part = threadIdx.x & 3;
    const float* wr = gw + (size_t)e * DIM;
    float s = 0.f;
    for (int k = part * 4; k < DIM; k += 16) {
        float4 a = *(const float4*)(sx + k);
        float4 b = *(const float4*)(wr + k);
        s += a.x * b.x + a.y * b.y + a.z * b.z + a.w * b.w;
    }
    s += __shfl_down_sync(0xffffffffu, s, 2, 4);
    s += __shfl_down_sync(0xffffffffu, s, 1, 4);
    if (part == 0) slog[e] = s;
    __syncthreads();

    if (threadIdx.x < 32) {
        float sc = slog[threadIdx.x];
        float m = sc;
        for (int o = 16; o; o >>= 1) m = fmaxf(m, __shfl_xor_sync(0xffffffffu, m, o));
        float p = expf(sc - m);
        float sum = p;
        for (int o = 16; o; o >>= 1) sum += __shfl_xor_sync(0xffffffffu, sum, o);
        float prob = p / sum;
        float v = prob;
        for (int r = 0; r < TOPK; r++) {
            float mv = v;
            for (int o = 16; o; o >>= 1) mv = fmaxf(mv, __shfl_xor_sync(0xffffffffu, mv, o));
            unsigned bal = __ballot_sync(0xffffffffu, v == mv);
            int idx = __ffs(bal) - 1;   // lowest index on tie == jax top_k
            if (threadIdx.x == 0) {
                g_topi[t * TOPK + r] = idx;
                g_topw[t * TOPK + r] = mv;
                atomicAdd(&g_cnt[idx], 1);
            }
            if (threadIdx.x == idx) v = -1.f;
        }
    }
}

// ---------------- kernel 2: offsets + tile map (serial, tiny) ----------------
__global__ void k_build() {
    if (blockIdx.x == 0 && threadIdx.x == 0) {
        int off = 0;
        for (int e = 0; e < NEXP; e++) { g_off[e] = off; off += g_cnt[e]; }
        g_off[NEXP] = off;
        int nt = 0;
        for (int e = 0; e < NEXP; e++) {
            int n = g_cnt[e], base = g_off[e];
            for (int r0 = 0; r0 < n; r0 += BM) {
                g_tile_e[nt]  = e;
                g_tile_r0[nt] = base + r0;
                g_tile_n[nt]  = min(BM, n - r0);
                nt++;
            }
        }
        g_ntiles = nt;
    }
}

// ---------------- kernel 3: deterministic token scatter (1 warp per expert) ----------------
__global__ __launch_bounds__(32) void k_scatter() {
    int e = blockIdx.x;
    int lane = threadIdx.x;
    int base = g_off[e];
    for (int t0 = 0; t0 < TT; t0 += 32) {
        int t = t0 + lane;
        float w = 0.f; bool f = false;
        #pragma unroll
        for (int k = 0; k < TOPK; k++)
            if (g_topi[t * TOPK + k] == e) { f = true; w = g_topw[t * TOPK + k]; }
        unsigned bal = __ballot_sync(0xffffffffu, f);
        int pos = base + __popc(bal & ((1u << lane) - 1u));
        if (f) { g_tok[pos] = t; g_wt[pos] = w; }
        base += __popc(bal);
    }
}

// ---------------- up kernel: h = silu(X@W1^T) * (X@W3^T) ----------------
// Tile: BM=128 rows x BN=64 cols, 256 threads, per-thread 8x4 for BOTH matrices.
template<bool SHARED>
__global__ __launch_bounds__(256) void k_up(const float* __restrict__ x,
                                            const float* __restrict__ w1,
                                            const float* __restrict__ w3) {
    const int NI = SHARED ? SHIN : INTER;
    __shared__ float sA[16][BM];
    __shared__ float sB1[16][64];
    __shared__ float sB3[16][64];
    __shared__ int   stok[BM];

    int tile = blockIdx.x;
    int e = 0, r0, nvalid = BM;
    if (!SHARED) {
        if (tile >= g_ntiles) return;
        e = g_tile_e[tile]; r0 = g_tile_r0[tile]; nvalid = g_tile_n[tile];
    } else {
        r0 = tile * BM;
    }
    int tid = threadIdx.x;
    if (tid < BM) {
        if (SHARED) stok[tid] = r0 + tid;
        else        stok[tid] = (tid < nvalid) ? g_tok[r0 + tid] : -1;
    }
    __syncthreads();

    int jblk = blockIdx.y * 64;

    // loader mapping
    int lrow  = tid >> 1;          // 0..127 (A rows)
    int lhalf = (tid & 1) * 8;     // 0 or 8 (k offset)
    int ltok  = stok[lrow];
    const float* pa = (ltok >= 0) ? x + (size_t)ltok * DIM + lhalf : nullptr;

    int bj = tid >> 2;             // 0..63 (B rows = inter cols)
    int bk = (tid & 3) * 4;        // 0,4,8,12
    const float* pb1 = w1 + ((size_t)e * NI + jblk + bj) * DIM + bk;
    const float* pb3 = w3 + ((size_t)e * NI + jblk + bj) * DIM + bk;

    // compute mapping
    int ty = tid >> 4, tx = tid & 15;
    int rr = ty * 8, cc = tx * 4;

    float acc1[8][4]; float acc3[8][4];
    #pragma unroll
    for (int i = 0; i < 8; i++)
        #pragma unroll
        for (int j = 0; j < 4; j++) { acc1[i][j] = 0.f; acc3[i][j] = 0.f; }

    float4 ra0, ra1, rb1, rb3;
    const float4 z4 = make_float4(0.f, 0.f, 0.f, 0.f);
    // prefetch kb=0
    if (pa) { ra0 = *(const float4*)(pa + 0); ra1 = *(const float4*)(pa + 4); }
    else    { ra0 = z4; ra1 = z4; }
    rb1 = *(const float4*)(pb1 + 0);
    rb3 = *(const float4*)(pb3 + 0);

    for (int kb = 0; kb < DIM; kb += 16) {
        __syncthreads();
        sA[lhalf + 0][lrow] = ra0.x; sA[lhalf + 1][lrow] = ra0.y;
        sA[lhalf + 2][lrow] = ra0.z; sA[lhalf + 3][lrow] = ra0.w;
        sA[lhalf + 4][lrow] = ra1.x; sA[lhalf + 5][lrow] = ra1.y;
        sA[lhalf + 6][lrow] = ra1.z; sA[lhalf + 7][lrow] = ra1.w;
        sB1[bk + 0][bj] = rb1.x; sB1[bk + 1][bj] = rb1.y;
        sB1[bk + 2][bj] = rb1.z; sB1[bk + 3][bj] = rb1.w;
        sB3[bk + 0][bj] = rb3.x; sB3[bk + 1][bj] = rb3.y;
        sB3[bk + 2][bj] = rb3.z; sB3[bk + 3][bj] = rb3.w;
        __syncthreads();

        int kn = kb + 16;
        if (kn < DIM) {
            if (pa) { ra0 = *(const float4*)(pa + kn); ra1 = *(const float4*)(pa + kn + 4); }
            else    { ra0 = z4; ra1 = z4; }
            rb1 = *(const float4*)(pb1 + kn);
            rb3 = *(const float4*)(pb3 + kn);
        }

        #pragma unroll
        for (int k = 0; k < 16; k++) {
            float4 aa0 = *(const float4*)&sA[k][rr];
            float4 aa1 = *(const float4*)&sA[k][rr + 4];
            float4 b1v = *(const float4*)&sB1[k][cc];
            float4 b3v = *(const float4*)&sB3[k][cc];
            float a[8] = {aa0.x, aa0.y, aa0.z, aa0.w, aa1.x, aa1.y, aa1.z, aa1.w};
            float c1[4] = {b1v.x, b1v.y, b1v.z, b1v.w};
            float c3[4] = {b3v.x, b3v.y, b3v.z, b3v.w};
            #pragma unroll
            for (int i = 0; i < 8; i++)
                #pragma unroll
                for (int j = 0; j < 4; j++) {
                    acc1[i][j] += a[i] * c1[j];
                    acc3[i][j] += a[i] * c3[j];
                }
        }
    }

    // epilogue: silu(h1) * h3
    #pragma unroll
    for (int i = 0; i < 8; i++) {
        int r = rr + i;
        if (r < nvalid) {
            float4 hv;
            hv.x = silu_f(acc1[i][0]) * acc3[i][0];
            hv.y = silu_f(acc1[i][1]) * acc3[i][1];
            hv.z = silu_f(acc1[i][2]) * acc3[i][2];
            hv.w = silu_f(acc1[i][3]) * acc3[i][3];
            float* dst = (SHARED ? g_hs + (size_t)(r0 + r) * SHIN
                                 : g_h  + (size_t)(r0 + r) * INTER) + jblk + cc;
            *(float4*)dst = hv;
        }
    }
}

// ---------------- down kernel: out (+)= (H @ W2^T) * wt ----------------
// Tile: BM=128 rows x BN=128 cols, 256 threads, per-thread 8x8.
template<bool SHARED>
__global__ __launch_bounds__(256) void k_down(const float* __restrict__ w2,
                                              float* __restrict__ out) {
    const int KD = SHARED ? SHIN : INTER;
    __shared__ float sA[16][BM];
    __shared__ float sB[16][BM];
    __shared__ int   stok[BM];
    __shared__ float swt[BM];

    int tile = blockIdx.x;
    int e = 0, r0, nvalid = BM;
    if (!SHARED) {
        if (tile >= g_ntiles) return;
        e = g_tile_e[tile]; r0 = g_tile_r0[tile]; nvalid = g_tile_n[tile];
    } else {
        r0 = tile * BM;
    }
    int tid = threadIdx.x;
    if (tid < BM) {
        if (SHARED) { stok[tid] = r0 + tid; swt[tid] = 1.f; }
        else {
            int ok = (tid < nvalid);
            stok[tid] = ok ? g_tok[r0 + tid] : -1;
            swt[tid]  = ok ? g_wt[r0 + tid]  : 0.f;
        }
    }
    __syncthreads();

    int dblk = blockIdx.y * BM;

    int lrow  = tid >> 1;
    int lhalf = (tid & 1) * 8;
    bool arow_ok = SHARED || (lrow < nvalid);
    const float* pa = SHARED ? g_hs + (size_t)(r0 + lrow) * SHIN + lhalf
                             : (arow_ok ? g_h + (size_t)(r0 + lrow) * INTER + lhalf : nullptr);
    const float* pb = w2 + ((size_t)e * DIM + dblk + lrow) * KD + lhalf;

    int ty = tid >> 4, tx = tid & 15;
    int rr = ty * 8, cc = tx * 8;

    float acc[8][8];
    #pragma unroll
    for (int i = 0; i < 8; i++)
        #pragma unroll
        for (int j = 0; j < 8; j++) acc[i][j] = 0.f;

    float4 ra0, ra1, rb0, rb1;
    const float4 z4 = make_float4(0.f, 0.f, 0.f, 0.f);
    if (pa) { ra0 = *(const float4*)(pa + 0); ra1 = *(const float4*)(pa + 4); }
    else    { ra0 = z4; ra1 = z4; }
    rb0 = *(const float4*)(pb + 0);
    rb1 = *(const float4*)(pb + 4);

    for (int kb = 0; kb < KD; kb += 16) {
        __syncthreads();
        sA[lhalf + 0][lrow] = ra0.x; sA[lhalf + 1][lrow] = ra0.y;
        sA[lhalf + 2][lrow] = ra0.z; sA[lhalf + 3][lrow] = ra0.w;
        sA[lhalf + 4][lrow] = ra1.x; sA[lhalf + 5][lrow] = ra1.y;
        sA[lhalf + 6][lrow] = ra1.z; sA[lhalf + 7][lrow] = ra1.w;
        sB[lhalf + 0][lrow] = rb0.x; sB[lhalf + 1][lrow] = rb0.y;
        sB[lhalf + 2][lrow] = rb0.z; sB[lhalf + 3][lrow] = rb0.w;
        sB[lhalf + 4][lrow] = rb1.x; sB[lhalf + 5][lrow] = rb1.y;
        sB[lhalf + 6][lrow] = rb1.z; sB[lhalf + 7][lrow] = rb1.w;
        __syncthreads();

        int kn = kb + 16;
        if (kn < KD) {
            if (pa) { ra0 = *(const float4*)(pa + kn); ra1 = *(const float4*)(pa + kn + 4); }
            else    { ra0 = z4; ra1 = z4; }
            rb0 = *(const float4*)(pb + kn);
            rb1 = *(const float4*)(pb + kn + 4);
        }

        #pragma unroll
        for (int k = 0; k < 16; k++) {
            float4 aa0 = *(const float4*)&sA[k][rr];
            float4 aa1 = *(const float4*)&sA[k][rr + 4];
            float4 bb0 = *(const float4*)&sB[k][cc];
            float4 bb1v = *(const float4*)&sB[k][cc + 4];
            float a[8] = {aa0.x, aa0.y, aa0.z, aa0.w, aa1.x, aa1.y, aa1.z, aa1.w};
            float b[8] = {bb0.x, bb0.y, bb0.z, bb0.w, bb1v.x, bb1v.y, bb1v.z, bb1v.w};
            #pragma unroll
            for (int i = 0; i < 8; i++)
                #pragma unroll
                for (int j = 0; j < 8; j++)
                    acc[i][j] += a[i] * b[j];
        }
    }

    #pragma unroll
    for (int i = 0; i < 8; i++) {
        int r = rr + i;
        int tok = stok[r];
        if (tok < 0) continue;
        float w = swt[r];
        float* dst = out + (size_t)tok * DIM + dblk + cc;
        if (SHARED) {
            float4 v0 = make_float4(acc[i][0], acc[i][1], acc[i][2], acc[i][3]);
            float4 v1 = make_float4(acc[i][4], acc[i][5], acc[i][6], acc[i][7]);
            *(float4*)(dst + 0) = v0;
            *(float4*)(dst + 4) = v1;
        } else {
            #pragma unroll
            for (int j = 0; j < 8; j++)
                atomicAdd(dst + j, acc[i][j] * w);
        }
    }
}

// ---------------- launch ----------------
extern "C" void kernel_launch(void* const* d_in, const int* in_sizes, int n_in,
                              void* d_out, int out_size) {
    const float* x   = (const float*)d_in[0];
    const float* gw  = (const float*)d_in[1];
    const float* w1  = (const float*)d_in[2];
    const float* w2  = (const float*)d_in[3];
    const float* w3  = (const float*)d_in[4];
    const float* sw1 = (const float*)d_in[5];
    const float* sw2 = (const float*)d_in[6];
    const float* sw3 = (const float*)d_in[7];
    float* out = (float*)d_out;

    k_zero<<<1, 32>>>();
    k_gate<<<TT, 128>>>(x, gw);
    k_build<<<1, 1>>>();
    k_scatter<<<NEXP, 32>>>();

    // routed up: grid 96 x (1024/64=16); shared up: 16 x (2048/64=32)
    k_up<false><<<dim3(MAXTILES, INTER / 64), 256>>>(x, w1, w3);
    k_up<true><<<dim3(TT / BM, SHIN / 64), 256>>>(x, sw1, sw3);

    // shared down writes out directly (must precede routed atomics)
    k_down<true><<<dim3(TT / BM, DIM / BM), 256>>>(sw2, out);
    k_down<false><<<dim3(MAXTILES, DIM / BM), 256>>>(w2, out);
}

// round 4
// speedup vs baseline: 3.8158x; 3.8158x over previous
#include <cuda_runtime.h>
#include <math.h>
#include <stdint.h>

#define TT 2048
#define DIM 2048
#define NEXP 32
#define TOPK 4
#define INTER 1024
#define SHIN 2048
#define NA (TT*TOPK)
#define BM 128
#define MAXTILES (NA/BM + NEXP)   /* 96 */
#define PADS 36                   /* smem row stride in floats */

// ---------------- device scratch ----------------
__device__ int   g_topi[TT*TOPK];
__device__ float g_topw[TT*TOPK];
__device__ int   g_cnt[NEXP];
__device__ int   g_off[NEXP+1];
__device__ int   g_tok[NA];
__device__ float g_wt[NA];
__device__ int   g_tile_e[MAXTILES];
__device__ int   g_tile_r0[MAXTILES];
__device__ int   g_tile_n[MAXTILES];
__device__ int   g_ntiles;
__device__ float g_h[(size_t)NA*INTER];
__device__ float g_hs[(size_t)TT*SHIN];

// ---------------- helpers ----------------
__device__ __forceinline__ uint32_t smem_u32(const void* p) {
    uint32_t a;
    asm("{ .reg .u64 t; cvta.to.shared.u64 t, %1; cvt.u32.u64 %0, t; }" : "=r"(a) : "l"(p));
    return a;
}
__device__ __forceinline__ uint32_t f2tf(float f) {
    uint32_t r; asm("cvt.rna.tf32.f32 %0, %1;" : "=r"(r) : "f"(f)); return r;
}
__device__ __forceinline__ void cp16(uint32_t dst, const void* src) {
    asm volatile("cp.async.cg.shared.global [%0], [%1], 16;" :: "r"(dst), "l"(src));
}
#define CP_COMMIT() asm volatile("cp.async.commit_group;" ::: "memory")
template<int N>
__device__ __forceinline__ void cp_wait() {
    asm volatile("cp.async.wait_group %0;" :: "n"(N) : "memory");
}
__device__ __forceinline__ void mma8(float* c, const uint32_t* a, const uint32_t* b) {
    asm volatile("mma.sync.aligned.m16n8k8.row.col.f32.tf32.tf32.f32 "
        "{%0,%1,%2,%3}, {%4,%5,%6,%7}, {%8,%9}, {%0,%1,%2,%3};"
        : "+f"(c[0]), "+f"(c[1]), "+f"(c[2]), "+f"(c[3])
        : "r"(a[0]), "r"(a[1]), "r"(a[2]), "r"(a[3]), "r"(b[0]), "r"(b[1]));
}
__device__ __forceinline__ float silu_f(float v) { return v / (1.0f + __expf(-v)); }

// ---------------- kernel 0: zero counters ----------------
__global__ void k_zero() {
    if (threadIdx.x < NEXP) g_cnt[threadIdx.x] = 0;
}

// ---------------- kernel 1: gate (fp32 exact) ----------------
__global__ __launch_bounds__(128) void k_gate(const float* __restrict__ x,
                                              const float* __restrict__ gw) {
    __shared__ float sx[DIM];
    __shared__ float slog[NEXP];
    int t = blockIdx.x;
    const float* xr = x + (size_t)t * DIM;
    for (int i = threadIdx.x * 4; i < DIM; i += 128 * 4)
        *(float4*)(sx + i) = *(const float4*)(xr + i);
    __syncthreads();

    int e = threadIdx.x >> 2, part = threadIdx.x & 3;
    const float* wr = gw + (size_t)e * DIM;
    float s = 0.f;
    for (int k = part * 4; k < DIM; k += 16) {
        float4 a = *(const float4*)(sx + k);
        float4 b = *(const float4*)(wr + k);
        s += a.x * b.x + a.y * b.y + a.z * b.z + a.w * b.w;
    }
    s += __shfl_down_sync(0xffffffffu, s, 2, 4);
    s += __shfl_down_sync(0xffffffffu, s, 1, 4);
    if (part == 0) slog[e] = s;
    __syncthreads();

    if (threadIdx.x < 32) {
        float sc = slog[threadIdx.x];
        float m = sc;
        for (int o = 16; o; o >>= 1) m = fmaxf(m, __shfl_xor_sync(0xffffffffu, m, o));
        float p = expf(sc - m);
        float sum = p;
        for (int o = 16; o; o >>= 1) sum += __shfl_xor_sync(0xffffffffu, sum, o);
        float v = p / sum;
        for (int r = 0; r < TOPK; r++) {
            float mv = v;
            for (int o = 16; o; o >>= 1) mv = fmaxf(mv, __shfl_xor_sync(0xffffffffu, mv, o));
            unsigned bal = __ballot_sync(0xffffffffu, v == mv);
            int idx = __ffs(bal) - 1;
            if (threadIdx.x == 0) {
                g_topi[t * TOPK + r] = idx;
                g_topw[t * TOPK + r] = mv;
                atomicAdd(&g_cnt[idx], 1);
            }
            if (threadIdx.x == idx) v = -1.f;
        }
    }
}

// ---------------- kernel 2: offsets + tile map ----------------
__global__ void k_build() {
    if (threadIdx.x == 0) {
        int off = 0;
        for (int e = 0; e < NEXP; e++) { g_off[e] = off; off += g_cnt[e]; }
        g_off[NEXP] = off;
        int nt = 0;
        for (int e = 0; e < NEXP; e++) {
            int n = g_cnt[e], base = g_off[e];
            for (int r0 = 0; r0 < n; r0 += BM) {
                g_tile_e[nt] = e; g_tile_r0[nt] = base + r0;
                g_tile_n[nt] = min(BM, n - r0); nt++;
            }
        }
        g_ntiles = nt;
    }
}

// ---------------- kernel 3: parallel deterministic scatter ----------------
__global__ __launch_bounds__(256) void k_scatter() {
    int e = blockIdx.x, tid = threadIdx.x, w = tid >> 5, lane = tid & 31;
    __shared__ int wc[8];
    int t0 = w * 256;
    int cnt = 0;
    for (int i = 0; i < 8; i++) {
        int t = t0 + i * 32 + lane;
        bool f = false;
        #pragma unroll
        for (int k = 0; k < TOPK; k++) if (g_topi[t * TOPK + k] == e) f = true;
        cnt += __popc(__ballot_sync(0xffffffffu, f));
    }
    if (lane == 0) wc[w] = cnt;
    __syncthreads();
    int base = g_off[e];
    for (int ww = 0; ww < w; ww++) base += wc[ww];
    for (int i = 0; i < 8; i++) {
        int t = t0 + i * 32 + lane;
        float wt = 0.f; bool f = false;
        #pragma unroll
        for (int k = 0; k < TOPK; k++)
            if (g_topi[t * TOPK + k] == e) { f = true; wt = g_topw[t * TOPK + k]; }
        unsigned bal = __ballot_sync(0xffffffffu, f);
        int pos = base + __popc(bal & ((1u << lane) - 1u));
        if (f) { g_tok[pos] = t; g_wt[pos] = wt; }
        base += __popc(bal);
    }
}

// ---------------- up kernel: mma.sync tf32 --------------------------------
// CTA tile: 128 tokens x (64 w1-cols + 64 w3-cols). 8 warps 4x2; warp 32x32 per matrix.
template<bool SHARED>
__global__ __launch_bounds__(256, 2) void k_up_mma(const float* __restrict__ x,
                                                   const float* __restrict__ w1,
                                                   const float* __restrict__ w3) {
    constexpr int NI = SHARED ? SHIN : INTER;
    constexpr int KC = 32;
    constexpr int NCH = DIM / KC;             // 64
    constexpr int ATILE = BM * PADS;          // floats
    constexpr int STAGE = 2 * ATILE;          // A + B(128 rows)

    extern __shared__ float sm[];
    __shared__ int s_tok[BM];

    int tile = blockIdx.x;
    int e = 0, r0, nvalid = BM;
    if (!SHARED) {
        if (tile >= g_ntiles) return;
        e = g_tile_e[tile]; r0 = g_tile_r0[tile]; nvalid = g_tile_n[tile];
    } else r0 = tile * BM;

    int tid = threadIdx.x, wid = tid >> 5, lane = tid & 31;
    int jblk = blockIdx.y * 64;
    int wm = wid & 3, wn = wid >> 2;          // warp grid 4 x 2
    int gq = lane >> 2, cq = lane & 3;        // quad row/col

    if (tid < BM)
        s_tok[tid] = SHARED ? (r0 + tid) : g_tok[r0 + min(tid, nvalid - 1)];
    __syncthreads();

    // loader: 8 x 16B segments per thread per chunk
    const float* gp[8];
    uint32_t so[8];
    uint32_t smu = smem_u32(sm);
    #pragma unroll
    for (int j = 0; j < 8; j++) {
        int id = tid + j * 256;               // 0..2047
        int m = id >> 10;                     // 0 = A, 1 = B
        int r = (id & 1023) >> 3;             // 0..127
        int s = id & 7;                       // 16B seg
        so[j] = (uint32_t)(m * ATILE + r * PADS + s * 4);
        if (m == 0) gp[j] = x + (size_t)s_tok[r] * DIM + s * 4;
        else if (r < 64) gp[j] = w1 + ((size_t)e * NI + jblk + r) * DIM + s * 4;
        else             gp[j] = w3 + ((size_t)e * NI + jblk + (r - 64)) * DIM + s * 4;
    }

    float acc1[2][4][4], acc3[2][4][4];
    #pragma unroll
    for (int i = 0; i < 2; i++)
        #pragma unroll
        for (int j = 0; j < 4; j++)
            #pragma unroll
            for (int q = 0; q < 4; q++) { acc1[i][j][q] = 0.f; acc3[i][j][q] = 0.f; }

    // prologue: chunk 0 -> stage 0
    #pragma unroll
    for (int j = 0; j < 8; j++) cp16((smu + so[j] * 4), gp[j]);
    CP_COMMIT();

    for (int c = 0; c < NCH; c++) {
        int st = c & 1;
        if (c + 1 < NCH) {
            int kb = (c + 1) * KC;
            #pragma unroll
            for (int j = 0; j < 8; j++)
                cp16((smu + ((st ^ 1) * STAGE + so[j]) * 4), gp[j] + kb);
            CP_COMMIT();
            cp_wait<1>();
        } else cp_wait<0>();
        __syncthreads();

        const float* sA = sm + st * STAGE;
        const float* sB = sm + st * STAGE + ATILE;

        #pragma unroll
        for (int ks = 0; ks < 4; ks++) {
            int kb = ks * 8;
            uint32_t a[2][4];
            #pragma unroll
            for (int i = 0; i < 2; i++) {
                int row = wm * 32 + i * 16 + gq;
                a[i][0] = f2tf(sA[row * PADS + kb + cq]);
                a[i][1] = f2tf(sA[(row + 8) * PADS + kb + cq]);
                a[i][2] = f2tf(sA[row * PADS + kb + 4 + cq]);
                a[i][3] = f2tf(sA[(row + 8) * PADS + kb + 4 + cq]);
            }
            uint32_t b1[4][2], b3[4][2];
            #pragma unroll
            for (int j = 0; j < 4; j++) {
                int nc = wn * 32 + j * 8 + gq;
                b1[j][0] = f2tf(sB[nc * PADS + kb + cq]);
                b1[j][1] = f2tf(sB[nc * PADS + kb + 4 + cq]);
                b3[j][0] = f2tf(sB[(nc + 64) * PADS + kb + cq]);
                b3[j][1] = f2tf(sB[(nc + 64) * PADS + kb + 4 + cq]);
            }
            #pragma unroll
            for (int i = 0; i < 2; i++)
                #pragma unroll
                for (int j = 0; j < 4; j++) {
                    mma8(acc1[i][j], a[i], b1[j]);
                    mma8(acc3[i][j], a[i], b3[j]);
                }
        }
        __syncthreads();
    }

    // epilogue: silu(h1)*h3 -> hidden buffer
    #pragma unroll
    for (int i = 0; i < 2; i++) {
        int rbase = wm * 32 + i * 16 + gq;
        #pragma unroll
        for (int j = 0; j < 4; j++) {
            int col = jblk + wn * 32 + j * 8 + 2 * cq;
            if (rbase < nvalid) {
                float2 o;
                o.x = silu_f(acc1[i][j][0]) * acc3[i][j][0];
                o.y = silu_f(acc1[i][j][1]) * acc3[i][j][1];
                float* dst = SHARED ? (g_hs + (size_t)(r0 + rbase) * SHIN + col)
                                    : (g_h  + (size_t)(r0 + rbase) * INTER + col);
                *(float2*)dst = o;
            }
            if (rbase + 8 < nvalid) {
                float2 o;
                o.x = silu_f(acc1[i][j][2]) * acc3[i][j][2];
                o.y = silu_f(acc1[i][j][3]) * acc3[i][j][3];
                float* dst = SHARED ? (g_hs + (size_t)(r0 + rbase + 8) * SHIN + col)
                                    : (g_h  + (size_t)(r0 + rbase + 8) * INTER + col);
                *(float2*)dst = o;
            }
        }
    }
}

// ---------------- down kernel: mma.sync tf32 ------------------------------
// CTA tile: 128 rows x 128 dim-cols. 8 warps 4x2; warp 32x64.
template<bool SHARED>
__global__ __launch_bounds__(256, 2) void k_down_mma(const float* __restrict__ w2,
                                                     float* __restrict__ out) {
    constexpr int KD = SHARED ? SHIN : INTER;
    constexpr int KC = 32;
    constexpr int NCH = KD / KC;              // 64 or 32
    constexpr int ATILE = BM * PADS;
    constexpr int STAGE = 2 * ATILE;

    extern __shared__ float sm[];
    __shared__ int   s_tok[BM];
    __shared__ float s_wtv[BM];

    int tile = blockIdx.x;
    int e = 0, r0, nvalid = BM;
    if (!SHARED) {
        if (tile >= g_ntiles) return;
        e = g_tile_e[tile]; r0 = g_tile_r0[tile]; nvalid = g_tile_n[tile];
    } else r0 = tile * BM;

    int tid = threadIdx.x, wid = tid >> 5, lane = tid & 31;
    int dblk = blockIdx.y * 128;
    int wm = wid & 3, wn = wid >> 2;
    int gq = lane >> 2, cq = lane & 3;

    if (tid < BM) {
        if (SHARED) { s_tok[tid] = r0 + tid; s_wtv[tid] = 1.f; }
        else {
            int ok = tid < nvalid;
            s_tok[tid] = ok ? g_tok[r0 + tid] : 0;
            s_wtv[tid] = ok ? g_wt[r0 + tid]  : 0.f;
        }
    }
    __syncthreads();

    const float* gp[8];
    uint32_t so[8];
    uint32_t smu = smem_u32(sm);
    #pragma unroll
    for (int j = 0; j < 8; j++) {
        int id = tid + j * 256;
        int m = id >> 10;
        int r = (id & 1023) >> 3;
        int s = id & 7;
        so[j] = (uint32_t)(m * ATILE + r * PADS + s * 4);
        if (m == 0) gp[j] = SHARED ? (g_hs + (size_t)(r0 + r) * SHIN + s * 4)
                                   : (g_h + (size_t)min(r0 + r, NA - 1) * INTER + s * 4);
        else        gp[j] = w2 + ((size_t)e * DIM + dblk + r) * KD + s * 4;
    }

    float acc[2][8][4];
    #pragma unroll
    for (int i = 0; i < 2; i++)
        #pragma unroll
        for (int j = 0; j < 8; j++)
            #pragma unroll
            for (int q = 0; q < 4; q++) acc[i][j][q] = 0.f;

    #pragma unroll
    for (int j = 0; j < 8; j++) cp16((smu + so[j] * 4), gp[j]);
    CP_COMMIT();

    for (int c = 0; c < NCH; c++) {
        int st = c & 1;
        if (c + 1 < NCH) {
            int kb = (c + 1) * KC;
            #pragma unroll
            for (int j = 0; j < 8; j++)
                cp16((smu + ((st ^ 1) * STAGE + so[j]) * 4), gp[j] + kb);
            CP_COMMIT();
            cp_wait<1>();
        } else cp_wait<0>();
        __syncthreads();

        const float* sA = sm + st * STAGE;
        const float* sB = sm + st * STAGE + ATILE;

        #pragma unroll
        for (int ks = 0; ks < 4; ks++) {
            int kb = ks * 8;
            uint32_t a[2][4];
            #pragma unroll
            for (int i = 0; i < 2; i++) {
                int row = wm * 32 + i * 16 + gq;
                a[i][0] = f2tf(sA[row * PADS + kb + cq]);
                a[i][1] = f2tf(sA[(row + 8) * PADS + kb + cq]);
                a[i][2] = f2tf(sA[row * PADS + kb + 4 + cq]);
                a[i][3] = f2tf(sA[(row + 8) * PADS + kb + 4 + cq]);
            }
            #pragma unroll
            for (int j = 0; j < 8; j++) {
                int nc = wn * 64 + j * 8 + gq;
                uint32_t b[2];
                b[0] = f2tf(sB[nc * PADS + kb + cq]);
                b[1] = f2tf(sB[nc * PADS + kb + 4 + cq]);
                mma8(acc[0][j], a[0], b);
                mma8(acc[1][j], a[1], b);
            }
        }
        __syncthreads();
    }

    #pragma unroll
    for (int i = 0; i < 2; i++) {
        int rbase = wm * 32 + i * 16 + gq;
        #pragma unroll
        for (int j = 0; j < 8; j++) {
            int col = dblk + wn * 64 + j * 8 + 2 * cq;
            #pragma unroll
            for (int half = 0; half < 2; half++) {
                int r = rbase + half * 8;
                if (r >= nvalid) continue;
                int tok = s_tok[r];
                float wt = s_wtv[r];
                float* dst = out + (size_t)tok * DIM + col;
                float v0 = acc[i][j][half * 2 + 0];
                float v1 = acc[i][j][half * 2 + 1];
                if (SHARED) {
                    float2 o; o.x = v0; o.y = v1;
                    *(float2*)dst = o;
                } else {
                    atomicAdd(dst + 0, v0 * wt);
                    atomicAdd(dst + 1, v1 * wt);
                }
            }
        }
    }
}

// ---------------- launch ----------------
extern "C" void kernel_launch(void* const* d_in, const int* in_sizes, int n_in,
                              void* d_out, int out_size) {
    const float* x   = (const float*)d_in[0];
    const float* gw  = (const float*)d_in[1];
    const float* w1  = (const float*)d_in[2];
    const float* w2  = (const float*)d_in[3];
    const float* w3  = (const float*)d_in[4];
    const float* sw1 = (const float*)d_in[5];
    const float* sw2 = (const float*)d_in[6];
    const float* sw3 = (const float*)d_in[7];
    float* out = (float*)d_out;

    const int smBytes = 2 * 2 * BM * PADS * 4;   // 73728
    cudaFuncSetAttribute((const void*)k_up_mma<false>,   cudaFuncAttributeMaxDynamicSharedMemorySize, smBytes);
    cudaFuncSetAttribute((const void*)k_up_mma<true>,    cudaFuncAttributeMaxDynamicSharedMemorySize, smBytes);
    cudaFuncSetAttribute((const void*)k_down_mma<false>, cudaFuncAttributeMaxDynamicSharedMemorySize, smBytes);
    cudaFuncSetAttribute((const void*)k_down_mma<true>,  cudaFuncAttributeMaxDynamicSharedMemorySize, smBytes);

    k_zero<<<1, 32>>>();
    k_gate<<<TT, 128>>>(x, gw);
    k_build<<<1, 1>>>();
    k_scatter<<<NEXP, 256>>>();

    k_up_mma<false><<<dim3(MAXTILES, INTER / 64), 256, smBytes>>>(x, w1, w3);
    k_up_mma<true><<<dim3(TT / BM, SHIN / 64), 256, smBytes>>>(x, sw1, sw3);

    k_down_mma<true><<<dim3(TT / BM, DIM / 128), 256, smBytes>>>(sw2, out);
    k_down_mma<false><<<dim3(MAXTILES, DIM / 128), 256, smBytes>>>(w2, out);
}